// round 12
// baseline (speedup 1.0000x reference)
#include <cuda_runtime.h>
#include <cuda_fp16.h>
#include <cstdint>
#include <cstddef>

#define TT 64
#define BB 512
#define DD 512
#define HH 2048

// ---------------- scratch (device globals) ---------------------------------
__device__ __align__(16) float  g_ycur[BB * DD];
__device__ __align__(16) float  g_acc [BB * DD];
__device__ __align__(16) __half g_a   [BB * DD];          // gemm1 A operand
__device__ __align__(16) __half g_h   [(size_t)BB * HH];  // hidden activations
__device__ __align__(16) __half g_W1h [(size_t)DD * HH];
__device__ __align__(16) __half g_W2h [(size_t)HH * DD];
__device__ __align__(16) float  g_p2[8][(size_t)BB * DD]; // gemm2 split-K partials
__device__ int g_c1[8];          // per gemm1 row-block completion (monotonic per replay)
__device__ int g_cnt2[32];       // per gemm2 tile arrival counter (self-resetting)

// ---------------- ptx helpers ----------------------------------------------
__device__ __forceinline__ uint32_t su32(const void* p) {
    return (uint32_t)__cvta_generic_to_shared(p);
}
#define CPA16(d, s) asm volatile("cp.async.cg.shared.global [%0], [%1], 16;" :: "r"(d), "l"(s))
#define CPC()       asm volatile("cp.async.commit_group;" ::: "memory")
#define WAITG(n)    asm volatile("cp.async.wait_group %0;" :: "n"(n) : "memory")

__device__ __forceinline__ void ldsm_x4(uint32_t a[4], uint32_t addr) {
    asm volatile("ldmatrix.sync.aligned.m8n8.x4.shared.b16 {%0,%1,%2,%3}, [%4];"
                 : "=r"(a[0]), "=r"(a[1]), "=r"(a[2]), "=r"(a[3]) : "r"(addr));
}
__device__ __forceinline__ void ldsm_x4_t(uint32_t a[4], uint32_t addr) {
    asm volatile("ldmatrix.sync.aligned.m8n8.x4.trans.shared.b16 {%0,%1,%2,%3}, [%4];"
                 : "=r"(a[0]), "=r"(a[1]), "=r"(a[2]), "=r"(a[3]) : "r"(addr));
}
__device__ __forceinline__ void mma_fp16(float c[4], const uint32_t a[4],
                                         uint32_t b0, uint32_t b1) {
    asm volatile(
        "mma.sync.aligned.m16n8k16.row.col.f32.f16.f16.f32 "
        "{%0,%1,%2,%3},{%4,%5,%6,%7},{%8,%9},{%0,%1,%2,%3};"
        : "+f"(c[0]), "+f"(c[1]), "+f"(c[2]), "+f"(c[3])
        : "r"(a[0]), "r"(a[1]), "r"(a[2]), "r"(a[3]), "r"(b0), "r"(b1));
}

// ---------------- init / convert -------------------------------------------
__global__ void init_state(const float* __restrict__ y0, float* __restrict__ out) {
    int idx = blockIdx.x * blockDim.x + threadIdx.x;
    float4 v = ((const float4*)y0)[idx];
    ((float4*)out)[idx] = v;
    ((float4*)g_ycur)[idx] = v;
    __half2* a2 = (__half2*)g_a;
    a2[idx * 2]     = __floats2half2_rn(v.x, v.y);
    a2[idx * 2 + 1] = __floats2half2_rn(v.z, v.w);
    if (blockIdx.x == 0) {
        if (threadIdx.x < 8)  g_c1[threadIdx.x] = 0;
        if (threadIdx.x < 32) g_cnt2[threadIdx.x] = 0;
    }
}
__global__ void convert_w(const float* __restrict__ src, __half* __restrict__ dst) {
    int idx = blockIdx.x * blockDim.x + threadIdx.x;
    float4 v = ((const float4*)src)[idx];
    __half2* d2 = (__half2*)dst;
    d2[idx * 2]     = __floats2half2_rn(v.x, v.y);
    d2[idx * 2 + 1] = __floats2half2_rn(v.z, v.w);
}

extern __shared__ char dyn_sm[];

// ---- gemm1 geometry: 64x128 tile, 256 thr, BK=64, 4-stage ------------------
#define A1PIT 72                        // 64 + 8 halves
#define B1PIT 136                       // 128 + 8 halves
#define ABY1 (64 * A1PIT * 2)           // 9216 B
#define STG1 (ABY1 + 64 * B1PIT * 2)    // 26624 B
#define SMEM_MAX (4 * STG1)             // 106496 B
#define NT1 8

// ---- gemm2 geometry: 64x128 tile, K=256, 256 thr, BK=32, 3-stage -----------
#define A2PIT 40                        // 32 + 8
#define B2PIT 136                       // 128 + 8
#define ABY2 (64 * A2PIT * 2)           // 5120 B
#define STG2 (ABY2 + 32 * B2PIT * 2)    // 13824 B
#define NT2 8

// ============================================================================
// Fused substage kernel.  Grid 384 x 256 thr.
//   bid <  128 : gemm1 tile (bm = (bid>>4)*64, bn = (bid&15)*128)
//   bid >= 128 : gemm2 tile (tm = id2>>5, n = (id2>>3)&3, kz = id2&7)
// ============================================================================
__global__ void __launch_bounds__(256, 2) stage_kernel(const float* __restrict__ b1,
                                                       const float* __restrict__ b2,
                                                       const float* __restrict__ tarr,
                                                       float* __restrict__ out,
                                                       int s, float wgt, float cnext,
                                                       int first, int last, int need) {
    const int bid = blockIdx.x;
    const int tid = threadIdx.x, lane = tid & 31, warp = tid >> 5;
    const int g = lane >> 2, tg = lane & 3;
    const int wm = (warp >> 2) * 32, wn = (warp & 3) * 32;   // 2m x 4n, wt 32x32
    const int l16 = lane & 15, h16 = (lane >> 4) * 8;

    if (bid < 128) {
        // ================= gemm1: g_h = tanh(g_a @ W1 + b1) =================
        const int bm = (bid >> 4) * 64, bn = (bid & 15) * 128;

        auto loadStage = [&](int st, int kt) {
            char* Ab = dyn_sm + st * STG1;
            char* Bb = Ab + ABY1;
#pragma unroll
            for (int l = 0; l < 2; l++) {
                int j = tid + l * 256, r = j >> 3, c = (j & 7) * 8;
                CPA16(su32(Ab + (r * A1PIT + c) * 2),
                      g_a + (size_t)(bm + r) * DD + kt * 64 + c);
            }
#pragma unroll
            for (int l = 0; l < 4; l++) {
                int j = tid + l * 256, r = j >> 4, c = (j & 15) * 8;
                CPA16(su32(Bb + (r * B1PIT + c) * 2),
                      g_W1h + (size_t)(kt * 64 + r) * HH + bn + c);
            }
            CPC();
        };
        auto ldfA = [&](uint32_t Af[2][4], int st, int ks) {
            char* Ab = dyn_sm + st * STG1;
#pragma unroll
            for (int mi = 0; mi < 2; mi++)
                ldsm_x4(Af[mi], su32(Ab + ((wm + mi * 16 + l16) * A1PIT + ks + h16) * 2));
        };
        auto ldfB = [&](uint32_t Bf[4][2], int st, int ks) {
            char* Bb = dyn_sm + st * STG1 + ABY1;
#pragma unroll
            for (int bt = 0; bt < 2; bt++) {
                uint32_t r[4];
                ldsm_x4_t(r, su32(Bb + ((ks + l16) * B1PIT + wn + bt * 16 + h16) * 2));
                Bf[bt * 2][0] = r[0]; Bf[bt * 2][1] = r[1];
                Bf[bt * 2 + 1][0] = r[2]; Bf[bt * 2 + 1][1] = r[3];
            }
        };

        loadStage(0, 0); loadStage(1, 1); loadStage(2, 2);
        WAITG(2);
        __syncthreads();

        float acc[2][4][4];
#pragma unroll
        for (int mi = 0; mi < 2; mi++)
#pragma unroll
            for (int ni = 0; ni < 4; ni++)
#pragma unroll
                for (int r = 0; r < 4; r++) acc[mi][ni][r] = 0.f;

        uint32_t Af[2][2][4], Bf[2][4][2];
        ldfA(Af[0], 0, 0); ldfB(Bf[0], 0, 0);

        for (int kt = 0; kt < NT1; kt++) {
            const int st = kt & 3;
#pragma unroll
            for (int ks = 0; ks < 4; ks++) {
                const int pb = ks & 1;
                if (ks == 3) { WAITG(1); __syncthreads(); }
                const int nst = (ks < 3) ? st : ((kt + 1) & 3);
                const int nks = (ks < 3) ? (ks + 1) * 16 : 0;
                if (ks < 3 || kt + 1 < NT1) {
                    ldfA(Af[pb ^ 1], nst, nks);
                    ldfB(Bf[pb ^ 1], nst, nks);
                }
#pragma unroll
                for (int mi = 0; mi < 2; mi++)
#pragma unroll
                    for (int ni = 0; ni < 4; ni++)
                        mma_fp16(acc[mi][ni], Af[pb][mi], Bf[pb][ni][0], Bf[pb][ni][1]);
            }
            if (kt + 3 < NT1) loadStage((kt + 3) & 3, kt + 3); else CPC();
        }

#pragma unroll
        for (int mi = 0; mi < 2; mi++)
#pragma unroll
            for (int ni = 0; ni < 4; ni++) {
                int col = bn + wn + ni * 8 + tg * 2;
                float bc0 = __ldg(b1 + col), bc1 = __ldg(b1 + col + 1);
#pragma unroll
                for (int hr = 0; hr < 2; hr++) {
                    int row = bm + wm + mi * 16 + g + hr * 8;
                    float v0 = tanhf(acc[mi][ni][hr * 2 + 0] + bc0);
                    float v1 = tanhf(acc[mi][ni][hr * 2 + 1] + bc1);
                    *(__half2*)&g_h[(size_t)row * HH + col] = __floats2half2_rn(v0, v1);
                }
            }
        __syncthreads();
        if (tid == 0) {
            __threadfence();
            atomicAdd(&g_c1[bid >> 4], 1);
        }
        return;
    }

    // =================== gemm2: k = dt*(g_h @ W2 + b2) ======================
    const int id2 = bid - 128;
    const int tm = id2 >> 5, n = (id2 >> 3) & 3, kz = id2 & 7;
    const int bm = tm * 64, bn = n * 128;

    // wait for this row-block's gemm1 tiles (16 of them)
    if (tid == 0) {
        while (atomicAdd(&g_c1[tm], 0) < need) __nanosleep(128);
        __threadfence();
    }
    __syncthreads();

    {
        auto loadStage = [&](int st, int kt) {
            char* Ab = dyn_sm + st * STG2;
            char* Bb = Ab + ABY2;
            {
                int r = tid >> 2, c = (tid & 3) * 8;
                CPA16(su32(Ab + (r * A2PIT + c) * 2),
                      g_h + (size_t)(bm + r) * HH + kz * 256 + kt * 32 + c);
            }
#pragma unroll
            for (int l = 0; l < 2; l++) {
                int j = tid + l * 256, r = j >> 4, c = (j & 15) * 8;
                CPA16(su32(Bb + (r * B2PIT + c) * 2),
                      g_W2h + (size_t)(kz * 256 + kt * 32 + r) * DD + bn + c);
            }
            CPC();
        };
        auto ldfA = [&](uint32_t Af[2][4], int st, int ks) {
            char* Ab = dyn_sm + st * STG2;
#pragma unroll
            for (int mi = 0; mi < 2; mi++)
                ldsm_x4(Af[mi], su32(Ab + ((wm + mi * 16 + l16) * A2PIT + ks + h16) * 2));
        };
        auto ldfB = [&](uint32_t Bf[4][2], int st, int ks) {
            char* Bb = dyn_sm + st * STG2 + ABY2;
#pragma unroll
            for (int bt = 0; bt < 2; bt++) {
                uint32_t r[4];
                ldsm_x4_t(r, su32(Bb + ((ks + l16) * B2PIT + wn + bt * 16 + h16) * 2));
                Bf[bt * 2][0] = r[0]; Bf[bt * 2][1] = r[1];
                Bf[bt * 2 + 1][0] = r[2]; Bf[bt * 2 + 1][1] = r[3];
            }
        };

        loadStage(0, 0); loadStage(1, 1); loadStage(2, 2);
        WAITG(2);
        __syncthreads();

        float acc[2][4][4];
#pragma unroll
        for (int mi = 0; mi < 2; mi++)
#pragma unroll
            for (int ni = 0; ni < 4; ni++)
#pragma unroll
                for (int r = 0; r < 4; r++) acc[mi][ni][r] = 0.f;

        uint32_t Af[2][2][4], Bf[2][4][2];
        ldfA(Af[0], 0, 0); ldfB(Bf[0], 0, 0);

        for (int kt = 0; kt < NT2; kt++) {
            const int st = kt % 3;
#pragma unroll
            for (int ks = 0; ks < 2; ks++) {
                const int pb = ks & 1;
                if (ks == 1) { WAITG(1); __syncthreads(); }
                const int nst = (ks == 0) ? st : ((kt + 1) % 3);
                const int nks = (ks == 0) ? 16 : 0;
                if (ks == 0 || kt + 1 < NT2) {
                    ldfA(Af[pb ^ 1], nst, nks);
                    ldfB(Bf[pb ^ 1], nst, nks);
                }
#pragma unroll
                for (int mi = 0; mi < 2; mi++)
#pragma unroll
                    for (int ni = 0; ni < 4; ni++)
                        mma_fp16(acc[mi][ni], Af[pb][mi], Bf[pb][ni][0], Bf[pb][ni][1]);
            }
            if (kt + 3 < NT2) loadStage((kt + 3) % 3, kt + 3); else CPC();
        }

        // publish fp32 partial
        float* dst = g_p2[kz];
#pragma unroll
        for (int mi = 0; mi < 2; mi++)
#pragma unroll
            for (int ni = 0; ni < 4; ni++) {
                int col = bn + wn + ni * 8 + tg * 2;
#pragma unroll
                for (int hr = 0; hr < 2; hr++) {
                    int row = bm + wm + mi * 16 + g + hr * 8;
                    *(float2*)&dst[(size_t)row * DD + col] =
                        make_float2(acc[mi][ni][hr * 2 + 0], acc[mi][ni][hr * 2 + 1]);
                }
            }
    }

    // last-arriver reduction (self-resetting counter)
    {
        __shared__ int s_last;
        __syncthreads();
        if (tid == 0) {
            __threadfence();
            int old = atomicAdd(&g_cnt2[tm * 4 + n], 1);
            s_last = (old == 7);
            if (s_last) atomicExch(&g_cnt2[tm * 4 + n], 0);
        }
        __syncthreads();
        if (!s_last) return;
        if (tid == 0) __threadfence();
        __syncthreads();
    }

    // combine 8 partials (fixed kz order -> deterministic) + RK4 epilogue
    const float inv6 = 1.0f / 6.0f;
#pragma unroll
    for (int q = 0; q < 4; q++) {
        int row = bm + (tid >> 4) + q * 16;
        int col = bn + (tid & 15) * 8;
        size_t off = (size_t)row * DD + col;
        float dt = __ldg(tarr + (size_t)(s + 1) * BB + row)
                 - __ldg(tarr + (size_t)s * BB + row);

        float sum[8];
        {
            float4 a = *(const float4*)&g_p2[0][off];
            float4 b = *(const float4*)&g_p2[0][off + 4];
            sum[0] = a.x; sum[1] = a.y; sum[2] = a.z; sum[3] = a.w;
            sum[4] = b.x; sum[5] = b.y; sum[6] = b.z; sum[7] = b.w;
        }
#pragma unroll
        for (int z = 1; z < 8; z++) {
            float4 a = *(const float4*)&g_p2[z][off];
            float4 b = *(const float4*)&g_p2[z][off + 4];
            sum[0] += a.x; sum[1] += a.y; sum[2] += a.z; sum[3] += a.w;
            sum[4] += b.x; sum[5] += b.y; sum[6] += b.z; sum[7] += b.w;
        }

        float kv[8];
#pragma unroll
        for (int e = 0; e < 8; e++)
            kv[e] = dt * (sum[e] + __ldg(b2 + col + e));

        float yc[8], av[8];
        *(float4*)&yc[0] = *(const float4*)&g_ycur[off];
        *(float4*)&yc[4] = *(const float4*)&g_ycur[off + 4];
        if (first) {
#pragma unroll
            for (int e = 0; e < 8; e++) av[e] = wgt * kv[e];
        } else {
            *(float4*)&av[0] = *(const float4*)&g_acc[off];
            *(float4*)&av[4] = *(const float4*)&g_acc[off + 4];
#pragma unroll
            for (int e = 0; e < 8; e++) av[e] += wgt * kv[e];
        }

        uint4 ah;
        if (!last) {
            *(float4*)&g_acc[off]     = *(const float4*)&av[0];
            *(float4*)&g_acc[off + 4] = *(const float4*)&av[4];
            __half2 h;
            h = __floats2half2_rn(yc[0] + cnext * kv[0], yc[1] + cnext * kv[1]);
            __builtin_memcpy(&ah.x, &h, 4);
            h = __floats2half2_rn(yc[2] + cnext * kv[2], yc[3] + cnext * kv[3]);
            __builtin_memcpy(&ah.y, &h, 4);
            h = __floats2half2_rn(yc[4] + cnext * kv[4], yc[5] + cnext * kv[5]);
            __builtin_memcpy(&ah.z, &h, 4);
            h = __floats2half2_rn(yc[6] + cnext * kv[6], yc[7] + cnext * kv[7]);
            __builtin_memcpy(&ah.w, &h, 4);
        } else {
            float yn[8];
#pragma unroll
            for (int e = 0; e < 8; e++) yn[e] = yc[e] + av[e] * inv6;
            *(float4*)&g_ycur[off]     = *(const float4*)&yn[0];
            *(float4*)&g_ycur[off + 4] = *(const float4*)&yn[4];
            *(float4*)&out[(size_t)(s + 1) * BB * DD + off]     = *(const float4*)&yn[0];
            *(float4*)&out[(size_t)(s + 1) * BB * DD + off + 4] = *(const float4*)&yn[4];
            __half2 h;
            h = __floats2half2_rn(yn[0], yn[1]); __builtin_memcpy(&ah.x, &h, 4);
            h = __floats2half2_rn(yn[2], yn[3]); __builtin_memcpy(&ah.y, &h, 4);
            h = __floats2half2_rn(yn[4], yn[5]); __builtin_memcpy(&ah.z, &h, 4);
            h = __floats2half2_rn(yn[6], yn[7]); __builtin_memcpy(&ah.w, &h, 4);
        }
        *(uint4*)&g_a[off] = ah;
    }
}

// ---------------------------------------------------------------------------
extern "C" void kernel_launch(void* const* d_in, const int* in_sizes, int n_in,
                              void* d_out, int out_size) {
    const float* y0 = (const float*)d_in[0];
    const float* t  = (const float*)d_in[1];
    const float* W1 = (const float*)d_in[2];
    const float* b1 = (const float*)d_in[3];
    const float* W2 = (const float*)d_in[4];
    const float* b2 = (const float*)d_in[5];
    float* out = (float*)d_out;

    cudaFuncSetAttribute(stage_kernel, cudaFuncAttributeMaxDynamicSharedMemorySize, SMEM_MAX);

    __half* w1h; cudaGetSymbolAddress((void**)&w1h, g_W1h);
    __half* w2h; cudaGetSymbolAddress((void**)&w2h, g_W2h);

    init_state<<<(BB * DD / 4) / 256, 256>>>(y0, out);
    convert_w<<<(DD * HH / 4) / 256, 256>>>(W1, w1h);
    convert_w<<<(HH * DD / 4) / 256, 256>>>(W2, w2h);

    const float ws[4] = {1.0f, 2.0f, 2.0f, 1.0f};
    const float cn[4] = {0.5f, 0.5f, 1.0f, 0.0f};

    for (int s = 0; s < TT - 1; ++s) {
        for (int i = 0; i < 4; ++i) {
            int gen = s * 4 + i + 1;
            stage_kernel<<<384, 256, SMEM_MAX>>>(b1, b2, t, out, s, ws[i], cn[i],
                                                 (i == 0) ? 1 : 0, (i == 3) ? 1 : 0,
                                                 16 * gen);
        }
    }
}

// round 13
// speedup vs baseline: 1.3798x; 1.3798x over previous
#include <cuda_runtime.h>
#include <cuda_fp16.h>
#include <cstdint>
#include <cstddef>

#define TT 64
#define BB 512
#define DD 512
#define HH 2048

// ---------------- scratch (device globals) ---------------------------------
__device__ __align__(16) float  g_ycur[BB * DD];
__device__ __align__(16) float  g_acc [BB * DD];
__device__ __align__(16) __half g_a   [BB * DD];          // gemm1 A operand
__device__ __align__(16) __half g_h   [(size_t)BB * HH];  // hidden activations
__device__ __align__(16) __half g_W1h [(size_t)DD * HH];
__device__ __align__(16) __half g_W2h [(size_t)HH * DD];
__device__ __align__(16) float  g_p2[8][(size_t)BB * DD]; // gemm2 split-K partials
__device__ int g_cnt2[64];       // per gemm2 tile arrival counter

// ---------------- ptx helpers ----------------------------------------------
__device__ __forceinline__ uint32_t su32(const void* p) {
    return (uint32_t)__cvta_generic_to_shared(p);
}
#define CPA16(d, s) asm volatile("cp.async.cg.shared.global [%0], [%1], 16;" :: "r"(d), "l"(s))
#define CPC()       asm volatile("cp.async.commit_group;" ::: "memory")
#define WAITG(n)    asm volatile("cp.async.wait_group %0;" :: "n"(n) : "memory")

__device__ __forceinline__ void ldsm_x4(uint32_t a[4], uint32_t addr) {
    asm volatile("ldmatrix.sync.aligned.m8n8.x4.shared.b16 {%0,%1,%2,%3}, [%4];"
                 : "=r"(a[0]), "=r"(a[1]), "=r"(a[2]), "=r"(a[3]) : "r"(addr));
}
__device__ __forceinline__ void ldsm_x4_t(uint32_t a[4], uint32_t addr) {
    asm volatile("ldmatrix.sync.aligned.m8n8.x4.trans.shared.b16 {%0,%1,%2,%3}, [%4];"
                 : "=r"(a[0]), "=r"(a[1]), "=r"(a[2]), "=r"(a[3]) : "r"(addr));
}
__device__ __forceinline__ void mma_fp16(float c[4], const uint32_t a[4],
                                         uint32_t b0, uint32_t b1) {
    asm volatile(
        "mma.sync.aligned.m16n8k16.row.col.f32.f16.f16.f32 "
        "{%0,%1,%2,%3},{%4,%5,%6,%7},{%8,%9},{%0,%1,%2,%3};"
        : "+f"(c[0]), "+f"(c[1]), "+f"(c[2]), "+f"(c[3])
        : "r"(a[0]), "r"(a[1]), "r"(a[2]), "r"(a[3]), "r"(b0), "r"(b1));
}

// ---------------- init / convert -------------------------------------------
__global__ void init_state(const float* __restrict__ y0, float* __restrict__ out) {
    int idx = blockIdx.x * blockDim.x + threadIdx.x;
    float4 v = ((const float4*)y0)[idx];
    ((float4*)out)[idx] = v;
    ((float4*)g_ycur)[idx] = v;
    __half2* a2 = (__half2*)g_a;
    a2[idx * 2]     = __floats2half2_rn(v.x, v.y);
    a2[idx * 2 + 1] = __floats2half2_rn(v.z, v.w);
    if (blockIdx.x == 0 && threadIdx.x < 64) g_cnt2[threadIdx.x] = 0;
}
__global__ void convert_w(const float* __restrict__ src, __half* __restrict__ dst) {
    int idx = blockIdx.x * blockDim.x + threadIdx.x;
    float4 v = ((const float4*)src)[idx];
    __half2* d2 = (__half2*)dst;
    d2[idx * 2]     = __floats2half2_rn(v.x, v.y);
    d2[idx * 2 + 1] = __floats2half2_rn(v.z, v.w);
}

extern __shared__ char dyn_sm[];

// ============================================================================
// GEMM1 (R7 shape): g_h = tanh(g_a[512x512] @ W1[512x2048] + b1)
// CTA 64x128, 256 thr, warps 2x4 (wt 32x32), BK=64, 4-stage cp.async.
// Grid (16, 8) = 128 CTAs.  Measured 10.46us.
// ============================================================================
#define A1PIT 72         // A smem pitch (halves): 64 + 8
#define B1PIT 136        // B smem pitch: 128 + 8
#define ABY1 (64 * A1PIT * 2)
#define STG1 (ABY1 + 64 * B1PIT * 2)      // 26624
#define SMEM1 (4 * STG1)                  // 106496
#define NT1 8

__global__ void __launch_bounds__(256, 1) gemm1_kernel(const float* __restrict__ b1) {
    const int tid = threadIdx.x, lane = tid & 31, warp = tid >> 5;
    const int g = lane >> 2, tg = lane & 3;
    const int wm = (warp >> 2) * 32, wn = (warp & 3) * 32;
    const int bm = blockIdx.y * 64, bn = blockIdx.x * 128;
    const int l16 = lane & 15, h16 = (lane >> 4) * 8;

    auto loadStage = [&](int st, int kt) {
        char* Ab = dyn_sm + st * STG1;
        char* Bb = Ab + ABY1;
#pragma unroll
        for (int l = 0; l < 2; l++) {
            int j = tid + l * 256, r = j >> 3, c = (j & 7) * 8;
            CPA16(su32(Ab + (r * A1PIT + c) * 2), g_a + (size_t)(bm + r) * DD + kt * 64 + c);
        }
#pragma unroll
        for (int l = 0; l < 4; l++) {
            int j = tid + l * 256, r = j >> 4, c = (j & 15) * 8;
            CPA16(su32(Bb + (r * B1PIT + c) * 2), g_W1h + (size_t)(kt * 64 + r) * HH + bn + c);
        }
        CPC();
    };
    auto ldfA = [&](uint32_t Af[2][4], int st, int ks) {
        char* Ab = dyn_sm + st * STG1;
#pragma unroll
        for (int mi = 0; mi < 2; mi++)
            ldsm_x4(Af[mi], su32(Ab + ((wm + mi * 16 + l16) * A1PIT + ks + h16) * 2));
    };
    auto ldfB = [&](uint32_t Bf[4][2], int st, int ks) {
        char* Bb = dyn_sm + st * STG1 + ABY1;
#pragma unroll
        for (int bt = 0; bt < 2; bt++) {
            uint32_t r[4];
            ldsm_x4_t(r, su32(Bb + ((ks + l16) * B1PIT + wn + bt * 16 + h16) * 2));
            Bf[bt * 2][0] = r[0]; Bf[bt * 2][1] = r[1];
            Bf[bt * 2 + 1][0] = r[2]; Bf[bt * 2 + 1][1] = r[3];
        }
    };

    loadStage(0, 0); loadStage(1, 1); loadStage(2, 2);
    WAITG(2);
    __syncthreads();

    float acc[2][4][4];
#pragma unroll
    for (int mi = 0; mi < 2; mi++)
#pragma unroll
        for (int ni = 0; ni < 4; ni++)
#pragma unroll
            for (int r = 0; r < 4; r++) acc[mi][ni][r] = 0.f;

    uint32_t Af[2][2][4], Bf[2][4][2];
    ldfA(Af[0], 0, 0); ldfB(Bf[0], 0, 0);

    for (int kt = 0; kt < NT1; kt++) {
        const int st = kt & 3;
#pragma unroll
        for (int ks = 0; ks < 4; ks++) {
            const int pb = ks & 1;
            if (ks == 3) { WAITG(1); __syncthreads(); }
            const int nst = (ks < 3) ? st : ((kt + 1) & 3);
            const int nks = (ks < 3) ? (ks + 1) * 16 : 0;
            if (ks < 3 || kt + 1 < NT1) {
                ldfA(Af[pb ^ 1], nst, nks);
                ldfB(Bf[pb ^ 1], nst, nks);
            }
#pragma unroll
            for (int mi = 0; mi < 2; mi++)
#pragma unroll
                for (int ni = 0; ni < 4; ni++)
                    mma_fp16(acc[mi][ni], Af[pb][mi], Bf[pb][ni][0], Bf[pb][ni][1]);
        }
        if (kt + 3 < NT1) loadStage((kt + 3) & 3, kt + 3); else CPC();
    }

    // epilogue: tanh(acc + b1) -> half2 stores
#pragma unroll
    for (int mi = 0; mi < 2; mi++)
#pragma unroll
        for (int ni = 0; ni < 4; ni++) {
            int col = bn + wn + ni * 8 + tg * 2;
            float bc0 = __ldg(b1 + col), bc1 = __ldg(b1 + col + 1);
#pragma unroll
            for (int hr = 0; hr < 2; hr++) {
                int row = bm + wm + mi * 16 + g + hr * 8;
                float v0 = tanhf(acc[mi][ni][hr * 2 + 0] + bc0);
                float v1 = tanhf(acc[mi][ni][hr * 2 + 1] + bc1);
                *(__half2*)&g_h[(size_t)row * HH + col] = __floats2half2_rn(v0, v1);
            }
        }
}

// ============================================================================
// GEMM2 (R11 shape): C = g_h[512x2048] @ W2[2048x512]; split-K=8 (K=256/CTA).
// CTA 64x64, 128 thr, warps 2x2 (wt 32x32), BK=32, 3-stage.
// Grid (8, 8, 8) = 512 CTAs.  Last arriver sums 8 partials in fixed kz order
// (deterministic) + RK4 epilogue.  Measured ~7.4us.
// ============================================================================
#define A2PIT 40                        // 32 + 8
#define B2PIT 72                        // 64 + 8
#define ABY2 (64 * A2PIT * 2)           // 5120 B
#define BBY2 (32 * B2PIT * 2)           // 4608 B
#define STG2 (ABY2 + BBY2)              // 9728 B
#define SMEM2 (3 * STG2)                // 29184 B
#define NT2 8

__global__ void __launch_bounds__(128, 4) gemm2_kernel(const float* __restrict__ b2,
                                                       const float* __restrict__ tarr,
                                                       float* __restrict__ out,
                                                       int s, float wgt, float cnext,
                                                       int first, int last) {
    const int bm = blockIdx.y * 64, bn = blockIdx.x * 64, kz = blockIdx.z;
    const int tile = blockIdx.y * 8 + blockIdx.x;
    const int tid = threadIdx.x, lane = tid & 31, warp = tid >> 5;
    const int g = lane >> 2, tg = lane & 3;
    const int wm = (warp >> 1) * 32, wn = (warp & 1) * 32;
    const int l16 = lane & 15, h16 = (lane >> 4) * 8;

    const __half* Ag = g_h + (size_t)bm * HH + kz * 256;
    const __half* Bg = g_W2h + (size_t)(kz * 256) * DD + bn;

    auto loadStage = [&](int st, int kt) {
        char* Ab = dyn_sm + st * STG2;
        char* Bb = Ab + ABY2;
#pragma unroll
        for (int l = 0; l < 2; l++) {
            int j = tid + l * 128, r = j >> 2, c = (j & 3) * 8;
            CPA16(su32(Ab + (r * A2PIT + c) * 2), Ag + (size_t)r * HH + kt * 32 + c);
        }
#pragma unroll
        for (int l = 0; l < 2; l++) {
            int j = tid + l * 128, r = j >> 3, c = (j & 7) * 8;
            CPA16(su32(Bb + (r * B2PIT + c) * 2), Bg + (size_t)(kt * 32 + r) * DD + c);
        }
        CPC();
    };
    auto ldfA = [&](uint32_t Af[2][4], int st, int ks) {
        char* Ab = dyn_sm + st * STG2;
#pragma unroll
        for (int mi = 0; mi < 2; mi++)
            ldsm_x4(Af[mi], su32(Ab + ((wm + mi * 16 + l16) * A2PIT + ks + h16) * 2));
    };
    auto ldfB = [&](uint32_t Bf[4][2], int st, int ks) {
        char* Bb = dyn_sm + st * STG2 + ABY2;
#pragma unroll
        for (int bt = 0; bt < 2; bt++) {
            uint32_t r[4];
            ldsm_x4_t(r, su32(Bb + ((ks + l16) * B2PIT + wn + bt * 16 + h16) * 2));
            Bf[bt * 2][0] = r[0]; Bf[bt * 2][1] = r[1];
            Bf[bt * 2 + 1][0] = r[2]; Bf[bt * 2 + 1][1] = r[3];
        }
    };

    loadStage(0, 0); loadStage(1, 1); loadStage(2, 2);
    WAITG(2);
    __syncthreads();

    float acc[2][4][4];
#pragma unroll
    for (int mi = 0; mi < 2; mi++)
#pragma unroll
        for (int ni = 0; ni < 4; ni++)
#pragma unroll
            for (int r = 0; r < 4; r++) acc[mi][ni][r] = 0.f;

    uint32_t Af[2][2][4], Bf[2][4][2];
    ldfA(Af[0], 0, 0); ldfB(Bf[0], 0, 0);

    for (int kt = 0; kt < NT2; kt++) {
        const int st = kt % 3;
#pragma unroll
        for (int ks = 0; ks < 2; ks++) {
            const int pb = ks & 1;
            if (ks == 1) { WAITG(1); __syncthreads(); }
            const int nst = (ks == 0) ? st : ((kt + 1) % 3);
            const int nks = (ks == 0) ? 16 : 0;
            if (ks == 0 || kt + 1 < NT2) {
                ldfA(Af[pb ^ 1], nst, nks);
                ldfB(Bf[pb ^ 1], nst, nks);
            }
#pragma unroll
            for (int mi = 0; mi < 2; mi++)
#pragma unroll
                for (int ni = 0; ni < 4; ni++)
                    mma_fp16(acc[mi][ni], Af[pb][mi], Bf[pb][ni][0], Bf[pb][ni][1]);
        }
        if (kt + 3 < NT2) loadStage((kt + 3) % 3, kt + 3); else CPC();
    }

    // publish partial
    {
        float* dst = g_p2[kz];
#pragma unroll
        for (int mi = 0; mi < 2; mi++)
#pragma unroll
            for (int ni = 0; ni < 4; ni++) {
                int col = bn + wn + ni * 8 + tg * 2;
#pragma unroll
                for (int hr = 0; hr < 2; hr++) {
                    int row = bm + wm + mi * 16 + g + hr * 8;
                    *(float2*)&dst[(size_t)row * DD + col] =
                        make_float2(acc[mi][ni][hr * 2 + 0], acc[mi][ni][hr * 2 + 1]);
                }
            }
    }

    // last-arriver reduction (threadFenceReduction; self-resetting counter)
    {
        __shared__ int s_last;
        __syncthreads();
        if (tid == 0) {
            __threadfence();
            int old = atomicAdd(&g_cnt2[tile], 1);
            s_last = (old == 7);
            if (s_last) atomicExch(&g_cnt2[tile], 0);
        }
        __syncthreads();
        if (!s_last) return;
        if (tid == 0) __threadfence();
        __syncthreads();
    }

    // combine + RK4 epilogue (128 thr x 32 elems over the 64x64 tile)
    const float inv6 = 1.0f / 6.0f;
#pragma unroll
    for (int q = 0; q < 4; q++) {
        int row = bm + (tid >> 3) + q * 16;
        int col = bn + (tid & 7) * 8;
        size_t off = (size_t)row * DD + col;
        float dt = __ldg(tarr + (size_t)(s + 1) * BB + row)
                 - __ldg(tarr + (size_t)s * BB + row);

        float sum[8];
        {
            float4 a = *(const float4*)&g_p2[0][off];
            float4 b = *(const float4*)&g_p2[0][off + 4];
            sum[0] = a.x; sum[1] = a.y; sum[2] = a.z; sum[3] = a.w;
            sum[4] = b.x; sum[5] = b.y; sum[6] = b.z; sum[7] = b.w;
        }
#pragma unroll
        for (int z = 1; z < 8; z++) {
            float4 a = *(const float4*)&g_p2[z][off];
            float4 b = *(const float4*)&g_p2[z][off + 4];
            sum[0] += a.x; sum[1] += a.y; sum[2] += a.z; sum[3] += a.w;
            sum[4] += b.x; sum[5] += b.y; sum[6] += b.z; sum[7] += b.w;
        }

        float kv[8];
#pragma unroll
        for (int e = 0; e < 8; e++)
            kv[e] = dt * (sum[e] + __ldg(b2 + col + e));

        float yc[8], av[8];
        *(float4*)&yc[0] = *(const float4*)&g_ycur[off];
        *(float4*)&yc[4] = *(const float4*)&g_ycur[off + 4];
        if (first) {
#pragma unroll
            for (int e = 0; e < 8; e++) av[e] = wgt * kv[e];
        } else {
            *(float4*)&av[0] = *(const float4*)&g_acc[off];
            *(float4*)&av[4] = *(const float4*)&g_acc[off + 4];
#pragma unroll
            for (int e = 0; e < 8; e++) av[e] += wgt * kv[e];
        }

        uint4 ah;
        if (!last) {
            *(float4*)&g_acc[off]     = *(const float4*)&av[0];
            *(float4*)&g_acc[off + 4] = *(const float4*)&av[4];
            __half2 h;
            h = __floats2half2_rn(yc[0] + cnext * kv[0], yc[1] + cnext * kv[1]);
            __builtin_memcpy(&ah.x, &h, 4);
            h = __floats2half2_rn(yc[2] + cnext * kv[2], yc[3] + cnext * kv[3]);
            __builtin_memcpy(&ah.y, &h, 4);
            h = __floats2half2_rn(yc[4] + cnext * kv[4], yc[5] + cnext * kv[5]);
            __builtin_memcpy(&ah.z, &h, 4);
            h = __floats2half2_rn(yc[6] + cnext * kv[6], yc[7] + cnext * kv[7]);
            __builtin_memcpy(&ah.w, &h, 4);
        } else {
            float yn[8];
#pragma unroll
            for (int e = 0; e < 8; e++) yn[e] = yc[e] + av[e] * inv6;
            *(float4*)&g_ycur[off]     = *(const float4*)&yn[0];
            *(float4*)&g_ycur[off + 4] = *(const float4*)&yn[4];
            *(float4*)&out[(size_t)(s + 1) * BB * DD + off]     = *(const float4*)&yn[0];
            *(float4*)&out[(size_t)(s + 1) * BB * DD + off + 4] = *(const float4*)&yn[4];
            __half2 h;
            h = __floats2half2_rn(yn[0], yn[1]); __builtin_memcpy(&ah.x, &h, 4);
            h = __floats2half2_rn(yn[2], yn[3]); __builtin_memcpy(&ah.y, &h, 4);
            h = __floats2half2_rn(yn[4], yn[5]); __builtin_memcpy(&ah.z, &h, 4);
            h = __floats2half2_rn(yn[6], yn[7]); __builtin_memcpy(&ah.w, &h, 4);
        }
        *(uint4*)&g_a[off] = ah;
    }
}

// ---------------------------------------------------------------------------
extern "C" void kernel_launch(void* const* d_in, const int* in_sizes, int n_in,
                              void* d_out, int out_size) {
    const float* y0 = (const float*)d_in[0];
    const float* t  = (const float*)d_in[1];
    const float* W1 = (const float*)d_in[2];
    const float* b1 = (const float*)d_in[3];
    const float* W2 = (const float*)d_in[4];
    const float* b2 = (const float*)d_in[5];
    float* out = (float*)d_out;

    cudaFuncSetAttribute(gemm1_kernel, cudaFuncAttributeMaxDynamicSharedMemorySize, SMEM1);
    cudaFuncSetAttribute(gemm2_kernel, cudaFuncAttributeMaxDynamicSharedMemorySize, SMEM2);

    __half* w1h; cudaGetSymbolAddress((void**)&w1h, g_W1h);
    __half* w2h; cudaGetSymbolAddress((void**)&w2h, g_W2h);

    init_state<<<(BB * DD / 4) / 256, 256>>>(y0, out);
    convert_w<<<(DD * HH / 4) / 256, 256>>>(W1, w1h);
    convert_w<<<(HH * DD / 4) / 256, 256>>>(W2, w2h);

    const float ws[4] = {1.0f, 2.0f, 2.0f, 1.0f};
    const float cn[4] = {0.5f, 0.5f, 1.0f, 0.0f};

    dim3 grid1(HH / 128, BB / 64);     // 16 x 8 = 128 CTAs
    dim3 grid2(DD / 64, BB / 64, 8);   // 8 x 8 x 8 = 512 CTAs

    for (int s = 0; s < TT - 1; ++s) {
        for (int i = 0; i < 4; ++i) {
            gemm1_kernel<<<grid1, 256, SMEM1>>>(b1);
            gemm2_kernel<<<grid2, 128, SMEM2>>>(b2, t, out, s, ws[i], cn[i],
                                                (i == 0) ? 1 : 0, (i == 3) ? 1 : 0);
        }
    }
}